// round 1
// baseline (speedup 1.0000x reference)
#include <cuda_runtime.h>

// Problem constants
#define M_TOK 2048
#define K_DIM 2048
#define N_DIM 1408
#define N_EXP 8
#define TOP_K 2
#define CAP   1024
#define N_ROWS (M_TOK * TOP_K)

// GEMM tiling
#define BM 128
#define BN 64
#define BK 16

// Scratch (device globals: allocation-free per harness rules)
__device__ int   g_cnt[N_EXP];
__device__ int   g_tok[N_EXP * CAP];
__device__ float g_gw [N_EXP * CAP];
__device__ float g_act[(size_t)N_EXP * CAP * N_DIM];   // ~46 MB SwiGLU activations

// ---------------------------------------------------------------------------
// init: zero output + expert counters
// ---------------------------------------------------------------------------
__global__ void init_kernel(float* __restrict__ out) {
    int i = blockIdx.x * 256 + threadIdx.x;
    if (i < M_TOK * K_DIM) out[i] = 0.0f;
    if (i < N_EXP) g_cnt[i] = 0;
}

// ---------------------------------------------------------------------------
// route: assign each (token, slot) a position inside its expert group.
// Order within an expert is irrelevant (final combine is a sum per token).
// ---------------------------------------------------------------------------
__global__ void route_kernel(const int* __restrict__ idx,
                             const float* __restrict__ gate) {
    int r = blockIdx.x * 256 + threadIdx.x;
    if (r >= N_ROWS) return;
    int e = idx[r];
    int p = atomicAdd(&g_cnt[e], 1);
    if (p < CAP) {
        g_tok[e * CAP + p] = r / TOP_K;
        g_gw [e * CAP + p] = gate[r];
    }
}

// ---------------------------------------------------------------------------
// GEMM1 (fused): act = silu(min(A@Gw^T, 10)) * clip(A@Uw^T, -10, 10)
// A rows gathered via g_tok. NT GEMM, both operands K-major.
// ---------------------------------------------------------------------------
__global__ void __launch_bounds__(256, 2) gemm1_kernel(
        const float* __restrict__ H,
        const float* __restrict__ GW,
        const float* __restrict__ UW) {
    const int e = blockIdx.z;
    int cnt = g_cnt[e]; if (cnt > CAP) cnt = CAP;
    const int m0 = blockIdx.y * BM;
    if (m0 >= cnt) return;
    const int n0 = blockIdx.x * BN;

    __shared__ float As [BK][BM];
    __shared__ float Bgs[BK][BN];
    __shared__ float Bus[BK][BN];

    const int tid = threadIdx.x;
    const int tx = tid & 15;   // n-group (4 cols)
    const int ty = tid >> 4;   // m-group (8 rows)

    // A loader: 2 float4 per thread (rows ar0, ar0+64)
    const int ar0 = tid >> 2;          // 0..63
    const int akg = (tid & 3) << 2;    // 0,4,8,12
    const float* pa0 = H + (size_t)g_tok[e * CAP + m0 + ar0     ] * K_DIM + akg;
    const float* pa1 = H + (size_t)g_tok[e * CAP + m0 + ar0 + 64] * K_DIM + akg;
    // B loader: 1 float4 per thread per matrix
    const int br  = tid >> 2;          // 0..63
    const int bkg = (tid & 3) << 2;
    const float* pg = GW + ((size_t)e * N_DIM + n0 + br) * K_DIM + bkg;
    const float* pu = UW + ((size_t)e * N_DIM + n0 + br) * K_DIM + bkg;

    float accG[8][4], accU[8][4];
#pragma unroll
    for (int i = 0; i < 8; i++)
#pragma unroll
        for (int j = 0; j < 4; j++) { accG[i][j] = 0.f; accU[i][j] = 0.f; }

    // prologue prefetch
    float4 ra0 = *(const float4*)(pa0);
    float4 ra1 = *(const float4*)(pa1);
    float4 rb0 = *(const float4*)(pg);
    float4 rb1 = *(const float4*)(pu);

    const int NKT = K_DIM / BK;   // 128
    for (int kt = 0; kt < NKT; ++kt) {
        As [akg + 0][ar0     ] = ra0.x; As [akg + 1][ar0     ] = ra0.y;
        As [akg + 2][ar0     ] = ra0.z; As [akg + 3][ar0     ] = ra0.w;
        As [akg + 0][ar0 + 64] = ra1.x; As [akg + 1][ar0 + 64] = ra1.y;
        As [akg + 2][ar0 + 64] = ra1.z; As [akg + 3][ar0 + 64] = ra1.w;
        Bgs[bkg + 0][br] = rb0.x; Bgs[bkg + 1][br] = rb0.y;
        Bgs[bkg + 2][br] = rb0.z; Bgs[bkg + 3][br] = rb0.w;
        Bus[bkg + 0][br] = rb1.x; Bus[bkg + 1][br] = rb1.y;
        Bus[bkg + 2][br] = rb1.z; Bus[bkg + 3][br] = rb1.w;
        __syncthreads();

        if (kt + 1 < NKT) {   // prefetch next tile (overlaps compute)
            int ko = (kt + 1) * BK;
            ra0 = *(const float4*)(pa0 + ko);
            ra1 = *(const float4*)(pa1 + ko);
            rb0 = *(const float4*)(pg + ko);
            rb1 = *(const float4*)(pu + ko);
        }

#pragma unroll
        for (int kk = 0; kk < BK; ++kk) {
            float4 av0 = *(const float4*)&As [kk][ty * 8];
            float4 av1 = *(const float4*)&As [kk][ty * 8 + 4];
            float4 bgv = *(const float4*)&Bgs[kk][tx * 4];
            float4 buv = *(const float4*)&Bus[kk][tx * 4];
            float a[8] = {av0.x, av0.y, av0.z, av0.w, av1.x, av1.y, av1.z, av1.w};
            float bg[4] = {bgv.x, bgv.y, bgv.z, bgv.w};
            float bu[4] = {buv.x, buv.y, buv.z, buv.w};
#pragma unroll
            for (int i = 0; i < 8; i++)
#pragma unroll
                for (int j = 0; j < 4; j++) {
                    accG[i][j] += a[i] * bg[j];
                    accU[i][j] += a[i] * bu[j];
                }
        }
        __syncthreads();
    }

    // epilogue: SwiGLU with reference clamps, write activations
#pragma unroll
    for (int i = 0; i < 8; i++) {
        int m = m0 + ty * 8 + i;
        if (m < cnt) {
            float4 o;
            float* po = (float*)&o;
#pragma unroll
            for (int j = 0; j < 4; j++) {
                float g = fminf(accG[i][j], 10.0f);
                float u = fminf(fmaxf(accU[i][j], -10.0f), 10.0f);
                float s = g / (1.0f + __expf(-g));   // silu
                po[j] = s * u;
            }
            *(float4*)(g_act + ((size_t)e * CAP + m) * N_DIM + n0 + tx * 4) = o;
        }
    }
}

// ---------------------------------------------------------------------------
// GEMM2: d = act @ down^T, epilogue scatters gate-weighted rows into out.
// ---------------------------------------------------------------------------
__global__ void __launch_bounds__(256, 2) gemm2_kernel(
        const float* __restrict__ DW,
        float* __restrict__ OUT) {
    const int e = blockIdx.z;
    int cnt = g_cnt[e]; if (cnt > CAP) cnt = CAP;
    const int m0 = blockIdx.y * BM;
    if (m0 >= cnt) return;
    const int n0 = blockIdx.x * BN;   // output K-dim tile

    __shared__ float As[BK][BM];
    __shared__ float Bs[BK][BN];

    const int tid = threadIdx.x;
    const int tx = tid & 15;
    const int ty = tid >> 4;

    const int ar0 = tid >> 2;
    const int akg = (tid & 3) << 2;
    const float* pa0 = g_act + ((size_t)e * CAP + m0 + ar0     ) * N_DIM + akg;
    const float* pa1 = g_act + ((size_t)e * CAP + m0 + ar0 + 64) * N_DIM + akg;
    const int br  = tid >> 2;
    const int bkg = (tid & 3) << 2;
    const float* pb = DW + ((size_t)e * K_DIM + n0 + br) * N_DIM + bkg;

    float acc[8][4];
#pragma unroll
    for (int i = 0; i < 8; i++)
#pragma unroll
        for (int j = 0; j < 4; j++) acc[i][j] = 0.f;

    float4 ra0 = *(const float4*)(pa0);
    float4 ra1 = *(const float4*)(pa1);
    float4 rb  = *(const float4*)(pb);

    const int NKT = N_DIM / BK;   // 88
    for (int kt = 0; kt < NKT; ++kt) {
        As[akg + 0][ar0     ] = ra0.x; As[akg + 1][ar0     ] = ra0.y;
        As[akg + 2][ar0     ] = ra0.z; As[akg + 3][ar0     ] = ra0.w;
        As[akg + 0][ar0 + 64] = ra1.x; As[akg + 1][ar0 + 64] = ra1.y;
        As[akg + 2][ar0 + 64] = ra1.z; As[akg + 3][ar0 + 64] = ra1.w;
        Bs[bkg + 0][br] = rb.x; Bs[bkg + 1][br] = rb.y;
        Bs[bkg + 2][br] = rb.z; Bs[bkg + 3][br] = rb.w;
        __syncthreads();

        if (kt + 1 < NKT) {
            int ko = (kt + 1) * BK;
            ra0 = *(const float4*)(pa0 + ko);
            ra1 = *(const float4*)(pa1 + ko);
            rb  = *(const float4*)(pb + ko);
        }

#pragma unroll
        for (int kk = 0; kk < BK; ++kk) {
            float4 av0 = *(const float4*)&As[kk][ty * 8];
            float4 av1 = *(const float4*)&As[kk][ty * 8 + 4];
            float4 bv  = *(const float4*)&Bs[kk][tx * 4];
            float a[8] = {av0.x, av0.y, av0.z, av0.w, av1.x, av1.y, av1.z, av1.w};
            float b[4] = {bv.x, bv.y, bv.z, bv.w};
#pragma unroll
            for (int i = 0; i < 8; i++)
#pragma unroll
                for (int j = 0; j < 4; j++) acc[i][j] += a[i] * b[j];
        }
        __syncthreads();
    }

    // combine epilogue: out[tok] += gate * d_row   (<= TOPK writers per element)
#pragma unroll
    for (int i = 0; i < 8; i++) {
        int m = m0 + ty * 8 + i;
        if (m < cnt) {
            int   t = g_tok[e * CAP + m];
            float w = g_gw [e * CAP + m];
            float* po = OUT + (size_t)t * K_DIM + n0 + tx * 4;
#pragma unroll
            for (int j = 0; j < 4; j++) atomicAdd(po + j, acc[i][j] * w);
        }
    }
}

// ---------------------------------------------------------------------------
extern "C" void kernel_launch(void* const* d_in, const int* in_sizes, int n_in,
                              void* d_out, int out_size) {
    const float* H   = (const float*)d_in[0];   // flat_h      (M, K)
    const int*   IDX = (const int*)  d_in[1];   // flat_idx    (M, TOPK)
    const float* G   = (const float*)d_in[2];   // flat_gate   (M, TOPK)
    const float* GW  = (const float*)d_in[3];   // gate_weight (E, N, K)
    const float* UW  = (const float*)d_in[4];   // up_weight   (E, N, K)
    const float* DW  = (const float*)d_in[5];   // down_weight (E, K, N)
    float* OUT = (float*)d_out;                 // (M, K) f32

    init_kernel <<<(M_TOK * K_DIM + 255) / 256, 256>>>(OUT);
    route_kernel<<<(N_ROWS + 255) / 256, 256>>>(IDX, G);

    dim3 g1(N_DIM / BN, CAP / BM, N_EXP);   // 22 x 8 x 8
    gemm1_kernel<<<g1, 256>>>(H, GW, UW);

    dim3 g2(K_DIM / BN, CAP / BM, N_EXP);   // 32 x 8 x 8
    gemm2_kernel<<<g2, 256>>>(DW, OUT);
}

// round 3
// speedup vs baseline: 2.7150x; 2.7150x over previous
#include <cuda_runtime.h>
#include <cstdint>

// ---------------- problem constants ----------------
#define M_TOK 2048
#define K_DIM 2048
#define N_DIM 1408
#define N_EXP 8
#define TOP_K 2
#define CAP   1024
#define N_ROWS (M_TOK * TOP_K)

#define SA 36          // padded smem row stride (floats): conflict-free frags

// ---------------- scratch ----------------
__device__ int   g_cnt[N_EXP];
__device__ int   g_tok[N_EXP * CAP];
__device__ float g_gw [N_EXP * CAP];
__device__ float g_act[(size_t)N_EXP * CAP * N_DIM];   // SwiGLU activations

// ---------------- helpers (all baseline sm_80+ ISA) ----------------
__device__ __forceinline__ uint32_t smem_u32(const void* p) {
    uint32_t a;
    asm("{ .reg .u64 t; cvta.to.shared.u64 t, %1; cvt.u32.u64 %0, t; }" : "=r"(a) : "l"(p));
    return a;
}
__device__ __forceinline__ void cp16(uint32_t s, const void* g) {
    asm volatile("cp.async.cg.shared.global [%0], [%1], 16;" :: "r"(s), "l"(g));
}
#define CP_COMMIT() asm volatile("cp.async.commit_group;" ::: "memory")
#define CP_WAIT1()  asm volatile("cp.async.wait_group 1;" ::: "memory")
#define CP_WAIT0()  asm volatile("cp.async.wait_group 0;" ::: "memory")

__device__ __forceinline__ uint32_t f2tf(float x) {   // round-to-nearest tf32
    uint32_t r; asm("cvt.rna.tf32.f32 %0, %1;" : "=r"(r) : "f"(x)); return r;
}
__device__ __forceinline__ void mma8(float* c, const uint32_t* a, const uint32_t* b) {
    asm volatile(
        "mma.sync.aligned.m16n8k8.row.col.f32.tf32.tf32.f32 "
        "{%0,%1,%2,%3},{%4,%5,%6,%7},{%8,%9},{%0,%1,%2,%3};"
        : "+f"(c[0]), "+f"(c[1]), "+f"(c[2]), "+f"(c[3])
        : "r"(a[0]), "r"(a[1]), "r"(a[2]), "r"(a[3]), "r"(b[0]), "r"(b[1]));
}
__device__ __forceinline__ float swiglu(float g, float u) {
    g = fminf(g, 10.0f);
    u = fminf(fmaxf(u, -10.0f), 10.0f);
    return (g / (1.0f + __expf(-g))) * u;
}

// ---------------- small kernels ----------------
__global__ void init_kernel(float* __restrict__ out) {
    int i = blockIdx.x * 256 + threadIdx.x;
    if (i < M_TOK * K_DIM) out[i] = 0.0f;
    if (i < N_EXP) g_cnt[i] = 0;
}
__global__ void route_kernel(const int* __restrict__ idx, const float* __restrict__ gate) {
    int r = blockIdx.x * 256 + threadIdx.x;
    if (r >= N_ROWS) return;
    int e = idx[r];
    int p = atomicAdd(&g_cnt[e], 1);
    if (p < CAP) {
        g_tok[e * CAP + p] = r / TOP_K;
        g_gw [e * CAP + p] = gate[r];
    }
}

// ---------------- smem layouts ----------------
// GEMM1 stage: A 128x32 (stride 36) + Bg 64x32 + Bu 64x32 = 9216 floats
#define G1_STAGE 9216
#define G1_GOFF  4608
#define G1_UOFF  6912
#define G1_SMEM  ((3 * G1_STAGE + 128) * 4)
// GEMM2 stage: A 128x32 + B 128x32 = 9216 floats
#define G2_STAGE 9216
#define G2_BOFF  4608
#define G2_SMEM  ((3 * G2_STAGE + 256) * 4)

extern __shared__ float smf[];

// ---------------------------------------------------------------------------
// GEMM1: G = A@GW^T, U = A@UW^T (CTA tile 128x64 each), SwiGLU -> g_act
// ---------------------------------------------------------------------------
__global__ void __launch_bounds__(256) gemm1_tc(
        const float* __restrict__ H, const float* __restrict__ GW,
        const float* __restrict__ UW) {
    const int e = blockIdx.z;
    int cnt = g_cnt[e]; if (cnt > CAP) cnt = CAP;
    const int m0 = blockIdx.y * 128;
    if (m0 >= cnt) return;
    const int n0 = blockIdx.x * 64;

    const int tid = threadIdx.x, lane = tid & 31, wid = tid >> 5;
    const int wm = wid >> 2, wn = wid & 3;      // warp tile: 64m x 16n (x2 mats)
    const int gq = lane >> 2, tg = lane & 3;

    int* stok = (int*)(smf + 3 * G1_STAGE);
    if (tid < 128) {
        int t = g_tok[e * CAP + m0 + tid];
        stok[tid] = ((unsigned)t < M_TOK) ? t : 0;
    }
    __syncthreads();

    const uint32_t su = smem_u32(smf);
    const float* pa[4]; uint32_t oa[4];
#pragma unroll
    for (int i = 0; i < 4; i++) {
        int fi = tid + i * 256, row = fi >> 3, c4 = fi & 7;
        pa[i] = H + (size_t)stok[row] * K_DIM + c4 * 4;
        oa[i] = (uint32_t)(row * SA + c4 * 4) * 4u;
    }
    const float* pg[2]; const float* pu[2]; uint32_t ob[2];
#pragma unroll
    for (int i = 0; i < 2; i++) {
        int fi = tid + i * 256, row = fi >> 3, c4 = fi & 7;
        pg[i] = GW + ((size_t)e * N_DIM + n0 + row) * K_DIM + c4 * 4;
        pu[i] = UW + ((size_t)e * N_DIM + n0 + row) * K_DIM + c4 * 4;
        ob[i] = (uint32_t)(row * SA + c4 * 4) * 4u;
    }

    float cG[4][2][4] = {}, cU[4][2][4] = {};

    auto load = [&](int kt, int st) {
        const int ko = kt * 32;
        const uint32_t sb = su + (uint32_t)st * (G1_STAGE * 4);
#pragma unroll
        for (int i = 0; i < 4; i++) cp16(sb + oa[i], pa[i] + ko);
#pragma unroll
        for (int i = 0; i < 2; i++) cp16(sb + G1_GOFF * 4 + ob[i], pg[i] + ko);
#pragma unroll
        for (int i = 0; i < 2; i++) cp16(sb + G1_UOFF * 4 + ob[i], pu[i] + ko);
        CP_COMMIT();
    };

    int ar[4], br[2];
#pragma unroll
    for (int i = 0; i < 4; i++) ar[i] = (wm * 64 + i * 16 + gq) * SA;
#pragma unroll
    for (int j = 0; j < 2; j++) br[j] = (wn * 16 + j * 8 + gq) * SA;

    const int NT = K_DIM / 32;   // 64
    load(0, 0); load(1, 1);

    for (int kt = 0; kt < NT; ++kt) {
        if (kt + 2 < NT) { CP_WAIT1(); } else { CP_WAIT0(); }
        __syncthreads();
        if (kt + 2 < NT) load(kt + 2, (kt + 2) % 3);

        const float* S  = smf + (kt % 3) * G1_STAGE;
        const float* Gs = S + G1_GOFF;
        const float* Us = S + G1_UOFF;
#pragma unroll
        for (int ks = 0; ks < 32; ks += 8) {
            uint32_t bg[2][2], bu[2][2];
#pragma unroll
            for (int j = 0; j < 2; j++) {
                bg[j][0] = f2tf(Gs[br[j] + ks + tg]);
                bg[j][1] = f2tf(Gs[br[j] + ks + tg + 4]);
                bu[j][0] = f2tf(Us[br[j] + ks + tg]);
                bu[j][1] = f2tf(Us[br[j] + ks + tg + 4]);
            }
#pragma unroll
            for (int i = 0; i < 4; i++) {
                uint32_t a[4];
                a[0] = f2tf(S[ar[i] + ks + tg]);
                a[1] = f2tf(S[ar[i] + 8 * SA + ks + tg]);
                a[2] = f2tf(S[ar[i] + ks + tg + 4]);
                a[3] = f2tf(S[ar[i] + 8 * SA + ks + tg + 4]);
#pragma unroll
                for (int j = 0; j < 2; j++) {
                    mma8(cG[i][j], a, bg[j]);
                    mma8(cU[i][j], a, bu[j]);
                }
            }
        }
    }

    // SwiGLU epilogue -> g_act
#pragma unroll
    for (int i = 0; i < 4; i++) {
        int r0 = wm * 64 + i * 16 + gq;
        int mg0 = m0 + r0, mg1 = mg0 + 8;
        float* row0 = g_act + ((size_t)e * CAP + mg0) * N_DIM + n0;
        float* row1 = g_act + ((size_t)e * CAP + mg1) * N_DIM + n0;
#pragma unroll
        for (int j = 0; j < 2; j++) {
            int col = wn * 16 + j * 8 + tg * 2;
            if (mg0 < cnt) {
                float2 o = make_float2(swiglu(cG[i][j][0], cU[i][j][0]),
                                       swiglu(cG[i][j][1], cU[i][j][1]));
                *(float2*)(row0 + col) = o;
            }
            if (mg1 < cnt) {
                float2 o = make_float2(swiglu(cG[i][j][2], cU[i][j][2]),
                                       swiglu(cG[i][j][3], cU[i][j][3]));
                *(float2*)(row1 + col) = o;
            }
        }
    }
}

// ---------------------------------------------------------------------------
// GEMM2: D = act@DW^T (CTA tile 128x128), scatter gate-weighted -> OUT
// ---------------------------------------------------------------------------
__global__ void __launch_bounds__(256) gemm2_tc(
        const float* __restrict__ DW, float* __restrict__ OUT) {
    const int e = blockIdx.z;
    int cnt = g_cnt[e]; if (cnt > CAP) cnt = CAP;
    const int m0 = blockIdx.y * 128;
    if (m0 >= cnt) return;
    const int n0 = blockIdx.x * 128;

    const int tid = threadIdx.x, lane = tid & 31, wid = tid >> 5;
    const int wm = wid >> 2, wn = wid & 3;      // warp tile: 64m x 32n
    const int gq = lane >> 2, tg = lane & 3;

    int*   stok  = (int*)  (smf + 3 * G2_STAGE);
    float* sgate = (float*)(smf + 3 * G2_STAGE + 128);
    if (tid < 128) {
        int t = g_tok[e * CAP + m0 + tid];
        stok[tid]  = ((unsigned)t < M_TOK) ? t : 0;
        sgate[tid] = g_gw[e * CAP + m0 + tid];
    }
    __syncthreads();

    const uint32_t su = smem_u32(smf);
    const float* pa[4]; uint32_t oa[4];
    const float* pb[4]; uint32_t obf[4];
#pragma unroll
    for (int i = 0; i < 4; i++) {
        int fi = tid + i * 256, row = fi >> 3, c4 = fi & 7;
        pa[i]  = g_act + ((size_t)e * CAP + m0 + row) * N_DIM + c4 * 4;
        oa[i]  = (uint32_t)(row * SA + c4 * 4) * 4u;
        pb[i]  = DW + ((size_t)e * K_DIM + n0 + row) * N_DIM + c4 * 4;
        obf[i] = (uint32_t)(row * SA + c4 * 4) * 4u;
    }

    float c[4][4][4] = {};

    auto load = [&](int kt, int st) {
        const int ko = kt * 32;
        const uint32_t sb = su + (uint32_t)st * (G2_STAGE * 4);
#pragma unroll
        for (int i = 0; i < 4; i++) cp16(sb + oa[i], pa[i] + ko);
#pragma unroll
        for (int i = 0; i < 4; i++) cp16(sb + G2_BOFF * 4 + obf[i], pb[i] + ko);
        CP_COMMIT();
    };

    int ar[4], br[4];
#pragma unroll
    for (int i = 0; i < 4; i++) ar[i] = (wm * 64 + i * 16 + gq) * SA;
#pragma unroll
    for (int j = 0; j < 4; j++) br[j] = (wn * 32 + j * 8 + gq) * SA;

    const int NT = N_DIM / 32;   // 44
    load(0, 0); load(1, 1);

    for (int kt = 0; kt < NT; ++kt) {
        if (kt + 2 < NT) { CP_WAIT1(); } else { CP_WAIT0(); }
        __syncthreads();
        if (kt + 2 < NT) load(kt + 2, (kt + 2) % 3);

        const float* S  = smf + (kt % 3) * G2_STAGE;
        const float* Bs = S + G2_BOFF;
#pragma unroll
        for (int ks = 0; ks < 32; ks += 8) {
            uint32_t b[4][2];
#pragma unroll
            for (int j = 0; j < 4; j++) {
                b[j][0] = f2tf(Bs[br[j] + ks + tg]);
                b[j][1] = f2tf(Bs[br[j] + ks + tg + 4]);
            }
#pragma unroll
            for (int i = 0; i < 4; i++) {
                uint32_t a[4];
                a[0] = f2tf(S[ar[i] + ks + tg]);
                a[1] = f2tf(S[ar[i] + 8 * SA + ks + tg]);
                a[2] = f2tf(S[ar[i] + ks + tg + 4]);
                a[3] = f2tf(S[ar[i] + 8 * SA + ks + tg + 4]);
#pragma unroll
                for (int j = 0; j < 4; j++) mma8(c[i][j], a, b[j]);
            }
        }
    }

    // combine epilogue: atomicAdd gate-weighted rows
#pragma unroll
    for (int i = 0; i < 4; i++) {
        int r0 = wm * 64 + i * 16 + gq, r1 = r0 + 8;
        bool v0 = (m0 + r0) < cnt, v1 = (m0 + r1) < cnt;
        int   t0 = stok[r0], t1 = stok[r1];
        float w0 = sgate[r0], w1 = sgate[r1];
        float* o0 = OUT + (size_t)t0 * K_DIM + n0;
        float* o1 = OUT + (size_t)t1 * K_DIM + n0;
#pragma unroll
        for (int j = 0; j < 4; j++) {
            int col = wn * 32 + j * 8 + tg * 2;
            if (v0) {
                atomicAdd(o0 + col,     c[i][j][0] * w0);
                atomicAdd(o0 + col + 1, c[i][j][1] * w0);
            }
            if (v1) {
                atomicAdd(o1 + col,     c[i][j][2] * w1);
                atomicAdd(o1 + col + 1, c[i][j][3] * w1);
            }
        }
    }
}

// ---------------------------------------------------------------------------
extern "C" void kernel_launch(void* const* d_in, const int* in_sizes, int n_in,
                              void* d_out, int out_size) {
    const float* H   = (const float*)d_in[0];
    const int*   IDX = (const int*)  d_in[1];
    const float* G   = (const float*)d_in[2];
    const float* GW  = (const float*)d_in[3];
    const float* UW  = (const float*)d_in[4];
    const float* DW  = (const float*)d_in[5];
    float* OUT = (float*)d_out;

    cudaFuncSetAttribute(gemm1_tc, cudaFuncAttributeMaxDynamicSharedMemorySize, G1_SMEM);
    cudaFuncSetAttribute(gemm2_tc, cudaFuncAttributeMaxDynamicSharedMemorySize, G2_SMEM);

    init_kernel <<<(M_TOK * K_DIM + 255) / 256, 256>>>(OUT);
    route_kernel<<<(N_ROWS + 255) / 256, 256>>>(IDX, G);

    dim3 g1(N_DIM / 64, CAP / 128, N_EXP);    // 22 x 8 x 8
    gemm1_tc<<<g1, 256, G1_SMEM>>>(H, GW, UW);

    dim3 g2(K_DIM / 128, CAP / 128, N_EXP);   // 16 x 8 x 8
    gemm2_tc<<<g2, 256, G2_SMEM>>>(DW, OUT);
}

// round 4
// speedup vs baseline: 3.8649x; 1.4235x over previous
#include <cuda_runtime.h>
#include <cuda_fp16.h>
#include <cstdint>

// ---------------- problem constants ----------------
#define M_TOK 2048
#define K_DIM 2048
#define N_DIM 1408
#define N_EXP 8
#define TOP_K 2
#define CAP   1024
#define N_ROWS (M_TOK * TOP_K)

// ---------------- scratch ----------------
__device__ int    g_cnt[N_EXP];
__device__ int    g_tok[N_EXP * CAP];
__device__ float  g_gw [N_EXP * CAP];
__device__ __half g_act[(size_t)N_EXP * CAP * N_DIM];   // fp16 activations (~23MB)

// ---------------- helpers (baseline sm_80 ISA only) ----------------
__device__ __forceinline__ uint32_t smem_u32(const void* p) {
    uint32_t a;
    asm("{ .reg .u64 t; cvta.to.shared.u64 t, %1; cvt.u32.u64 %0, t; }" : "=r"(a) : "l"(p));
    return a;
}
__device__ __forceinline__ void ldsm4(uint32_t* r, uint32_t addr) {
    asm volatile("ldmatrix.sync.aligned.m8n8.x4.shared.b16 {%0,%1,%2,%3}, [%4];"
                 : "=r"(r[0]), "=r"(r[1]), "=r"(r[2]), "=r"(r[3]) : "r"(addr));
}
__device__ __forceinline__ void mma16816(float* c, const uint32_t* a, uint32_t b0, uint32_t b1) {
    asm volatile("mma.sync.aligned.m16n8k16.row.col.f32.f16.f16.f32 "
        "{%0,%1,%2,%3},{%4,%5,%6,%7},{%8,%9},{%0,%1,%2,%3};"
        : "+f"(c[0]), "+f"(c[1]), "+f"(c[2]), "+f"(c[3])
        : "r"(a[0]), "r"(a[1]), "r"(a[2]), "r"(a[3]), "r"(b0), "r"(b1));
}
__device__ __forceinline__ uint32_t pk(float a, float b) {
    __half2 h = __floats2half2_rn(a, b);
    return *reinterpret_cast<uint32_t*>(&h);
}
__device__ __forceinline__ float swiglu(float g, float u) {
    g = fminf(g, 10.0f);
    u = fminf(fmaxf(u, -10.0f), 10.0f);
    return (g / (1.0f + __expf(-g))) * u;
}
// 64B rows of 32 fp16; 16B chunk c of row r lives at r*64 + ((c ^ ((r>>1)&3))<<4)
__device__ __forceinline__ uint32_t swz(int row, int c) {
    return (uint32_t)(row * 64 + ((c ^ ((row >> 1) & 3)) << 4));
}

// ---------------- small kernels ----------------
__global__ void init_kernel(float* __restrict__ out) {
    int i = blockIdx.x * 256 + threadIdx.x;
    if (i < M_TOK * K_DIM) out[i] = 0.0f;
    if (i < N_EXP) g_cnt[i] = 0;
}
__global__ void route_kernel(const int* __restrict__ idx, const float* __restrict__ gate) {
    int r = blockIdx.x * 256 + threadIdx.x;
    if (r >= N_ROWS) return;
    int e = idx[r];
    int p = atomicAdd(&g_cnt[e], 1);
    if (p < CAP) {
        g_tok[e * CAP + p] = r / TOP_K;
        g_gw [e * CAP + p] = gate[r];
    }
}

// stage = 16KB for both kernels; double buffered
#define STAGE_B 16384
extern __shared__ char smc[];

// ---------------------------------------------------------------------------
// GEMM1: G = A@GW^T, U = A@UW^T (CTA 128m x 64n, both mats), SwiGLU -> g_act
// stage layout: A[128 rows]@0, G[64]@8192, U[64]@12288 (rows of 32 fp16)
// ---------------------------------------------------------------------------
__global__ void __launch_bounds__(256, 2) gemm1_tc(
        const float* __restrict__ H, const float* __restrict__ GW,
        const float* __restrict__ UW) {
    const int e = blockIdx.z;
    int cnt = g_cnt[e]; if (cnt > CAP) cnt = CAP;
    const int m0 = blockIdx.y * 128;
    if (m0 >= cnt) return;
    const int n0 = blockIdx.x * 64;

    const int tid = threadIdx.x, lane = tid & 31, wid = tid >> 5;
    const int wm = wid >> 2, wn = wid & 3;            // warp: 64m x 16n (x2 mats)
    const int gq = lane >> 2, tg = lane & 3;
    const int lane15 = lane & 15, lhi = lane >> 4;

    int* stok = (int*)(smc + 2 * STAGE_B);
    if (tid < 128) {
        int t = g_tok[e * CAP + m0 + tid];
        stok[tid] = ((unsigned)t < M_TOK) ? t : 0;
    }
    __syncthreads();

    const uint32_t su = smem_u32(smc);

    // loader mapping
    const int arow = tid >> 1, ac = (tid & 1) * 2;              // A: 2 chunks
    const float* pa = H + (size_t)stok[arow] * K_DIM + ac * 8;
    const uint32_t soA0 = swz(arow, ac), soA1 = swz(arow, ac + 1);
    const int grow = tid >> 2, gc = tid & 3;                    // G/U: 1 chunk
    const float* pg = GW + ((size_t)e * N_DIM + n0 + grow) * K_DIM + gc * 8;
    const float* pu = UW + ((size_t)e * N_DIM + n0 + grow) * K_DIM + gc * 8;
    const uint32_t soG = 8192 + swz(grow, gc), soU = 12288 + swz(grow, gc);

    // ldmatrix row bases
    int aoff[4], axr[4];
#pragma unroll
    for (int i = 0; i < 4; i++) {
        int r = wm * 64 + i * 16 + lane15;
        aoff[i] = r * 64; axr[i] = (r >> 1) & 3;
    }
    const int brw = wn * 16 + lane15;
    const int boff = brw * 64, bxr = (brw >> 1) & 3;

    float cG[4][2][4] = {}, cU[4][2][4] = {};
    float4 ra[4], rg[2], ru[2];

    auto ldg = [&](int kt) {
        const int ko = kt * 32;
#pragma unroll
        for (int q = 0; q < 4; q++) ra[q] = *(const float4*)(pa + ko + q * 4);
#pragma unroll
        for (int q = 0; q < 2; q++) {
            rg[q] = *(const float4*)(pg + ko + q * 4);
            ru[q] = *(const float4*)(pu + ko + q * 4);
        }
    };
    auto sts = [&](int b) {
        char* sb = smc + b * STAGE_B;
        *(uint4*)(sb + soA0) = make_uint4(pk(ra[0].x, ra[0].y), pk(ra[0].z, ra[0].w),
                                          pk(ra[1].x, ra[1].y), pk(ra[1].z, ra[1].w));
        *(uint4*)(sb + soA1) = make_uint4(pk(ra[2].x, ra[2].y), pk(ra[2].z, ra[2].w),
                                          pk(ra[3].x, ra[3].y), pk(ra[3].z, ra[3].w));
        *(uint4*)(sb + soG)  = make_uint4(pk(rg[0].x, rg[0].y), pk(rg[0].z, rg[0].w),
                                          pk(rg[1].x, rg[1].y), pk(rg[1].z, rg[1].w));
        *(uint4*)(sb + soU)  = make_uint4(pk(ru[0].x, ru[0].y), pk(ru[0].z, ru[0].w),
                                          pk(ru[1].x, ru[1].y), pk(ru[1].z, ru[1].w));
    };

    const int NT = K_DIM / 32;   // 64
    ldg(0);
    for (int kt = 0; kt < NT; ++kt) {
        sts(kt & 1);
        __syncthreads();
        if (kt + 1 < NT) ldg(kt + 1);

        const uint32_t sb = su + (kt & 1) * STAGE_B;
#pragma unroll
        for (int kh = 0; kh < 2; ++kh) {
            const int ch = 2 * kh + lhi;
            uint32_t bg[4], bu[4];
            ldsm4(bg, sb + 8192  + boff + (((ch ^ bxr)) << 4));
            ldsm4(bu, sb + 12288 + boff + (((ch ^ bxr)) << 4));
#pragma unroll
            for (int i = 0; i < 4; i++) {
                uint32_t a[4];
                ldsm4(a, sb + aoff[i] + ((ch ^ axr[i]) << 4));
                mma16816(cG[i][0], a, bg[0], bg[2]);
                mma16816(cG[i][1], a, bg[1], bg[3]);
                mma16816(cU[i][0], a, bu[0], bu[2]);
                mma16816(cU[i][1], a, bu[1], bu[3]);
            }
        }
    }

    // SwiGLU epilogue -> fp16 act
#pragma unroll
    for (int i = 0; i < 4; i++) {
        int r0 = wm * 64 + i * 16 + gq;
        int mg0 = m0 + r0, mg1 = mg0 + 8;
        __half* row0 = g_act + ((size_t)e * CAP + mg0) * N_DIM + n0;
        __half* row1 = g_act + ((size_t)e * CAP + mg1) * N_DIM + n0;
#pragma unroll
        for (int j = 0; j < 2; j++) {
            int col = wn * 16 + j * 8 + tg * 2;
            if (mg0 < cnt)
                *(__half2*)(row0 + col) = __floats2half2_rn(
                    swiglu(cG[i][j][0], cU[i][j][0]), swiglu(cG[i][j][1], cU[i][j][1]));
            if (mg1 < cnt)
                *(__half2*)(row1 + col) = __floats2half2_rn(
                    swiglu(cG[i][j][2], cU[i][j][2]), swiglu(cG[i][j][3], cU[i][j][3]));
        }
    }
}

// ---------------------------------------------------------------------------
// GEMM2: D = act@DW^T (CTA 128m x 128n), scatter gate-weighted -> OUT
// stage layout: A[128 rows]@0, B[128 rows]@8192
// ---------------------------------------------------------------------------
__global__ void __launch_bounds__(256, 2) gemm2_tc(
        const float* __restrict__ DW, float* __restrict__ OUT) {
    const int e = blockIdx.z;
    int cnt = g_cnt[e]; if (cnt > CAP) cnt = CAP;
    const int m0 = blockIdx.y * 128;
    if (m0 >= cnt) return;
    const int n0 = blockIdx.x * 128;

    const int tid = threadIdx.x, lane = tid & 31, wid = tid >> 5;
    const int wm = wid >> 2, wn = wid & 3;            // warp: 64m x 32n
    const int gq = lane >> 2, tg = lane & 3;
    const int lane15 = lane & 15, lhi = lane >> 4;

    int*   stok  = (int*)  (smc + 2 * STAGE_B);
    float* sgate = (float*)(smc + 2 * STAGE_B + 512);
    if (tid < 128) {
        int t = g_tok[e * CAP + m0 + tid];
        stok[tid]  = ((unsigned)t < M_TOK) ? t : 0;
        sgate[tid] = g_gw[e * CAP + m0 + tid];
    }
    __syncthreads();

    const uint32_t su = smem_u32(smc);

    const int arow = tid >> 1, ac = (tid & 1) * 2;
    const __half* pa = g_act + ((size_t)e * CAP + m0 + arow) * N_DIM + ac * 8;
    const uint32_t soA0 = swz(arow, ac), soA1 = swz(arow, ac + 1);
    const float* pb = DW + ((size_t)e * K_DIM + n0 + arow) * N_DIM + ac * 8;
    const uint32_t soB0 = 8192 + soA0, soB1 = 8192 + soA1;

    int aoff[4], axr[4];
#pragma unroll
    for (int i = 0; i < 4; i++) {
        int r = wm * 64 + i * 16 + lane15;
        aoff[i] = r * 64; axr[i] = (r >> 1) & 3;
    }
    int boff[2], bxr[2];
#pragma unroll
    for (int j = 0; j < 2; j++) {
        int r = wn * 32 + j * 16 + lane15;
        boff[j] = 8192 + r * 64; bxr[j] = (r >> 1) & 3;
    }

    float c[4][4][4] = {};
    uint4  ha[2];
    float4 rb[4];

    auto ldg = [&](int kt) {
        const int ko = kt * 32;
        ha[0] = *(const uint4*)(pa + ko);
        ha[1] = *(const uint4*)(pa + ko + 8);
#pragma unroll
        for (int q = 0; q < 4; q++) rb[q] = *(const float4*)(pb + ko + q * 4);
    };
    auto sts = [&](int b) {
        char* sb = smc + b * STAGE_B;
        *(uint4*)(sb + soA0) = ha[0];
        *(uint4*)(sb + soA1) = ha[1];
        *(uint4*)(sb + soB0) = make_uint4(pk(rb[0].x, rb[0].y), pk(rb[0].z, rb[0].w),
                                          pk(rb[1].x, rb[1].y), pk(rb[1].z, rb[1].w));
        *(uint4*)(sb + soB1) = make_uint4(pk(rb[2].x, rb[2].y), pk(rb[2].z, rb[2].w),
                                          pk(rb[3].x, rb[3].y), pk(rb[3].z, rb[3].w));
    };

    const int NT = N_DIM / 32;   // 44
    ldg(0);
    for (int kt = 0; kt < NT; ++kt) {
        sts(kt & 1);
        __syncthreads();
        if (kt + 1 < NT) ldg(kt + 1);

        const uint32_t sb = su + (kt & 1) * STAGE_B;
#pragma unroll
        for (int kh = 0; kh < 2; ++kh) {
            const int ch = 2 * kh + lhi;
            uint32_t b0[4], b1[4];
            ldsm4(b0, sb + boff[0] + ((ch ^ bxr[0]) << 4));
            ldsm4(b1, sb + boff[1] + ((ch ^ bxr[1]) << 4));
#pragma unroll
            for (int i = 0; i < 4; i++) {
                uint32_t a[4];
                ldsm4(a, sb + aoff[i] + ((ch ^ axr[i]) << 4));
                mma16816(c[i][0], a, b0[0], b0[2]);
                mma16816(c[i][1], a, b0[1], b0[3]);
                mma16816(c[i][2], a, b1[0], b1[2]);
                mma16816(c[i][3], a, b1[1], b1[3]);
            }
        }
    }

    // combine epilogue
#pragma unroll
    for (int i = 0; i < 4; i++) {
        int r0 = wm * 64 + i * 16 + gq, r1 = r0 + 8;
        bool v0 = (m0 + r0) < cnt, v1 = (m0 + r1) < cnt;
        int   t0 = stok[r0], t1 = stok[r1];
        float w0 = sgate[r0], w1 = sgate[r1];
        float* o0 = OUT + (size_t)t0 * K_DIM + n0;
        float* o1 = OUT + (size_t)t1 * K_DIM + n0;
#pragma unroll
        for (int j = 0; j < 4; j++) {
            int col = wn * 32 + j * 8 + tg * 2;
            if (v0) {
                atomicAdd(o0 + col,     c[i][j][0] * w0);
                atomicAdd(o0 + col + 1, c[i][j][1] * w0);
            }
            if (v1) {
                atomicAdd(o1 + col,     c[i][j][2] * w1);
                atomicAdd(o1 + col + 1, c[i][j][3] * w1);
            }
        }
    }
}

// ---------------------------------------------------------------------------
extern "C" void kernel_launch(void* const* d_in, const int* in_sizes, int n_in,
                              void* d_out, int out_size) {
    const float* H   = (const float*)d_in[0];
    const int*   IDX = (const int*)  d_in[1];
    const float* G   = (const float*)d_in[2];
    const float* GW  = (const float*)d_in[3];
    const float* UW  = (const float*)d_in[4];
    const float* DW  = (const float*)d_in[5];
    float* OUT = (float*)d_out;

    const int g1s = 2 * STAGE_B + 512;
    const int g2s = 2 * STAGE_B + 1024;
    cudaFuncSetAttribute(gemm1_tc, cudaFuncAttributeMaxDynamicSharedMemorySize, g1s);
    cudaFuncSetAttribute(gemm2_tc, cudaFuncAttributeMaxDynamicSharedMemorySize, g2s);

    init_kernel <<<(M_TOK * K_DIM + 255) / 256, 256>>>(OUT);
    route_kernel<<<(N_ROWS + 255) / 256, 256>>>(IDX, G);

    dim3 g1(N_DIM / 64, CAP / 128, N_EXP);    // 22 x 8 x 8
    gemm1_tc<<<g1, 256, g1s>>>(H, GW, UW);

    dim3 g2(K_DIM / 128, CAP / 128, N_EXP);   // 16 x 8 x 8
    gemm2_tc<<<g2, 256, g2s>>>(DW, OUT);
}

// round 5
// speedup vs baseline: 4.9466x; 1.2799x over previous
#include <cuda_runtime.h>
#include <cuda_fp16.h>
#include <cstdint>

// ---------------- problem constants ----------------
#define M_TOK 2048
#define K_DIM 2048
#define N_DIM 1408
#define N_EXP 8
#define TOP_K 2
#define CAP   1024
#define N_ROWS (M_TOK * TOP_K)
#define W_ELEMS (N_EXP * N_DIM * K_DIM)        // per weight matrix

// ---------------- scratch ----------------
__device__ int    g_cnt[N_EXP];
__device__ int    g_slot[N_ROWS];                                  // e*CAP+p or -1
__device__ __half g_x16 [(size_t)N_EXP * CAP * K_DIM];             // dispatched rows fp16 (32MB)
__device__ __half g_act [(size_t)N_EXP * CAP * N_DIM];             // SwiGLU acts fp16 (23MB)
__device__ float  g_stage[(size_t)N_EXP * CAP * K_DIM];            // down output fp32 (64MB)
__device__ __half g_gw16[W_ELEMS];                                 // fp16 weights (46MB x3)
__device__ __half g_uw16[W_ELEMS];
__device__ __half g_dw16[W_ELEMS];

// ---------------- helpers (baseline sm_80 ISA) ----------------
__device__ __forceinline__ uint32_t smem_u32(const void* p) {
    uint32_t a;
    asm("{ .reg .u64 t; cvta.to.shared.u64 t, %1; cvt.u32.u64 %0, t; }" : "=r"(a) : "l"(p));
    return a;
}
__device__ __forceinline__ void cp16(uint32_t s, const void* g) {
    asm volatile("cp.async.cg.shared.global [%0], [%1], 16;" :: "r"(s), "l"(g));
}
#define CP_COMMIT() asm volatile("cp.async.commit_group;" ::: "memory")
#define CP_WAIT1()  asm volatile("cp.async.wait_group 1;" ::: "memory")
#define CP_WAIT0()  asm volatile("cp.async.wait_group 0;" ::: "memory")
__device__ __forceinline__ void ldsm4(uint32_t* r, uint32_t addr) {
    asm volatile("ldmatrix.sync.aligned.m8n8.x4.shared.b16 {%0,%1,%2,%3}, [%4];"
                 : "=r"(r[0]), "=r"(r[1]), "=r"(r[2]), "=r"(r[3]) : "r"(addr));
}
__device__ __forceinline__ void mma16816(float* c, const uint32_t* a, uint32_t b0, uint32_t b1) {
    asm volatile("mma.sync.aligned.m16n8k16.row.col.f32.f16.f16.f32 "
        "{%0,%1,%2,%3},{%4,%5,%6,%7},{%8,%9},{%0,%1,%2,%3};"
        : "+f"(c[0]), "+f"(c[1]), "+f"(c[2]), "+f"(c[3])
        : "r"(a[0]), "r"(a[1]), "r"(a[2]), "r"(a[3]), "r"(b0), "r"(b1));
}
__device__ __forceinline__ uint2 pk4(float4 v) {
    __half2 h0 = __floats2half2_rn(v.x, v.y), h1 = __floats2half2_rn(v.z, v.w);
    return make_uint2(*reinterpret_cast<uint32_t*>(&h0), *reinterpret_cast<uint32_t*>(&h1));
}
__device__ __forceinline__ float swiglu(float g, float u) {
    g = fminf(g, 10.0f);
    u = fminf(fmaxf(u, -10.0f), 10.0f);
    return (g / (1.0f + __expf(-g))) * u;
}
// smem tile: rows of 32 fp16 (64B), chunk c of row r at r*64 + ((c ^ ((r>>1)&3))<<4)
__device__ __forceinline__ uint32_t swz(int row, int c) {
    return (uint32_t)(row * 64 + ((c ^ ((row >> 1) & 3)) << 4));
}

// ---------------- prep kernels ----------------
__global__ void zero_cnt() { if (threadIdx.x < N_EXP) g_cnt[threadIdx.x] = 0; }

__global__ void route_kernel(const int* __restrict__ idx) {
    int r = blockIdx.x * 256 + threadIdx.x;
    if (r >= N_ROWS) return;
    int e = idx[r];
    int p = atomicAdd(&g_cnt[e], 1);
    g_slot[r] = (p < CAP) ? (e * CAP + p) : -1;
}

// one block per routed row: copy H[token] -> g_x16[slot] (fp32->fp16)
__global__ void __launch_bounds__(128) gather_x(const float* __restrict__ H) {
    const int r = blockIdx.x;
    const int s = g_slot[r];
    if (s < 0) return;
    const float4* src = (const float4*)(H + (size_t)(r >> 1) * K_DIM);
    uint2* dst = (uint2*)(g_x16 + (size_t)s * K_DIM);
#pragma unroll
    for (int i = 0; i < 4; i++) {
        int q = threadIdx.x + i * 128;
        dst[q] = pk4(src[q]);
    }
}

// fp32 -> fp16 weight conversion; blockIdx.y selects matrix
__global__ void __launch_bounds__(256) convw(const float* __restrict__ GW,
                                             const float* __restrict__ UW,
                                             const float* __restrict__ DW) {
    const float* src = (blockIdx.y == 0) ? GW : (blockIdx.y == 1) ? UW : DW;
    __half* dst = (blockIdx.y == 0) ? g_gw16 : (blockIdx.y == 1) ? g_uw16 : g_dw16;
    size_t q = (size_t)blockIdx.x * 256 + threadIdx.x;          // float4 index
    float4 v = ((const float4*)src)[q];
    ((uint2*)dst)[q] = pk4(v);
}

// ---------------- GEMMs ----------------
#define STAGE_B 16384
extern __shared__ char smc[];

// GEMM1: G = X@GW^T, U = X@UW^T (CTA 128m x 64n each), SwiGLU -> g_act
// stage: A(128rows)@0  G(64)@8192  U(64)@12288  (rows of 32 fp16)
__global__ void __launch_bounds__(256, 2) gemm1_tc() {
    const int e = blockIdx.z;
    int cnt = g_cnt[e]; if (cnt > CAP) cnt = CAP;
    const int m0 = blockIdx.y * 128;
    if (m0 >= cnt) return;
    const int n0 = blockIdx.x * 64;

    const int tid = threadIdx.x, lane = tid & 31, wid = tid >> 5;
    const int wm = wid >> 2, wn = wid & 3;
    const int gq = lane >> 2, tg = lane & 3;
    const int lane15 = lane & 15, lhi = lane >> 4;

    const uint32_t su = smem_u32(smc);

    // loaders: 4-lanes-per-row (64B contiguous gmem, conflict-free swizzled smem)
    const int lrow = tid >> 2, lc = tid & 3;
    const __half* pa0 = g_x16 + ((size_t)(e * CAP + m0) + lrow) * K_DIM + lc * 8;
    const __half* pa1 = pa0 + (size_t)64 * K_DIM;
    const __half* pg  = g_gw16 + ((size_t)e * N_DIM + n0 + lrow) * K_DIM + lc * 8;
    const __half* pu  = g_uw16 + ((size_t)e * N_DIM + n0 + lrow) * K_DIM + lc * 8;
    const uint32_t soA0 = swz(lrow, lc), soA1 = swz(lrow + 64, lc);
    const uint32_t soG = 8192 + swz(lrow, lc), soU = 12288 + swz(lrow, lc);

    auto load = [&](int kt, int st) {
        const uint32_t sb = su + (uint32_t)st * STAGE_B;
        const int ko = kt * 32;
        cp16(sb + soA0, pa0 + ko);
        cp16(sb + soA1, pa1 + ko);
        cp16(sb + soG,  pg  + ko);
        cp16(sb + soU,  pu  + ko);
        CP_COMMIT();
    };

    int aoff[4], axr[4];
#pragma unroll
    for (int i = 0; i < 4; i++) {
        int r = wm * 64 + i * 16 + lane15;
        aoff[i] = r * 64; axr[i] = (r >> 1) & 3;
    }
    const int brw = wn * 16 + lane15;
    const int boff = brw * 64, bxr = (brw >> 1) & 3;

    float cG[4][2][4] = {}, cU[4][2][4] = {};

    const int NT = K_DIM / 32;   // 64
    load(0, 0); load(1, 1);
    for (int kt = 0; kt < NT; ++kt) {
        if (kt + 2 < NT) { CP_WAIT1(); } else { CP_WAIT0(); }
        __syncthreads();
        if (kt + 2 < NT) load(kt + 2, (kt + 2) % 3);

        const uint32_t sb = su + (uint32_t)(kt % 3) * STAGE_B;
#pragma unroll
        for (int kh = 0; kh < 2; ++kh) {
            const int ch = 2 * kh + lhi;
            uint32_t bg[4], bu[4];
            ldsm4(bg, sb + 8192  + boff + ((ch ^ bxr) << 4));
            ldsm4(bu, sb + 12288 + boff + ((ch ^ bxr) << 4));
#pragma unroll
            for (int i = 0; i < 4; i++) {
                uint32_t a[4];
                ldsm4(a, sb + aoff[i] + ((ch ^ axr[i]) << 4));
                mma16816(cG[i][0], a, bg[0], bg[2]);
                mma16816(cG[i][1], a, bg[1], bg[3]);
                mma16816(cU[i][0], a, bu[0], bu[2]);
                mma16816(cU[i][1], a, bu[1], bu[3]);
            }
        }
    }

#pragma unroll
    for (int i = 0; i < 4; i++) {
        int r0 = wm * 64 + i * 16 + gq;
        int mg0 = m0 + r0, mg1 = mg0 + 8;
        __half* row0 = g_act + ((size_t)e * CAP + mg0) * N_DIM + n0;
        __half* row1 = g_act + ((size_t)e * CAP + mg1) * N_DIM + n0;
#pragma unroll
        for (int j = 0; j < 2; j++) {
            int col = wn * 16 + j * 8 + tg * 2;
            if (mg0 < cnt)
                *(__half2*)(row0 + col) = __floats2half2_rn(
                    swiglu(cG[i][j][0], cU[i][j][0]), swiglu(cG[i][j][1], cU[i][j][1]));
            if (mg1 < cnt)
                *(__half2*)(row1 + col) = __floats2half2_rn(
                    swiglu(cG[i][j][2], cU[i][j][2]), swiglu(cG[i][j][3], cU[i][j][3]));
        }
    }
}

// GEMM2: D = act@DW^T (CTA 128m x 128n) -> g_stage (plain stores, no atomics)
// stage: A(128rows)@0  B(128rows)@8192
__global__ void __launch_bounds__(256, 2) gemm2_tc() {
    const int e = blockIdx.z;
    int cnt = g_cnt[e]; if (cnt > CAP) cnt = CAP;
    const int m0 = blockIdx.y * 128;
    if (m0 >= cnt) return;
    const int n0 = blockIdx.x * 128;

    const int tid = threadIdx.x, lane = tid & 31, wid = tid >> 5;
    const int wm = wid >> 2, wn = wid & 3;
    const int gq = lane >> 2, tg = lane & 3;
    const int lane15 = lane & 15, lhi = lane >> 4;

    const uint32_t su = smem_u32(smc);

    const int lrow = tid >> 2, lc = tid & 3;
    const __half* pa0 = g_act + ((size_t)(e * CAP + m0) + lrow) * N_DIM + lc * 8;
    const __half* pa1 = pa0 + (size_t)64 * N_DIM;
    const __half* pb0 = g_dw16 + ((size_t)e * K_DIM + n0 + lrow) * N_DIM + lc * 8;
    const __half* pb1 = pb0 + (size_t)64 * N_DIM;
    const uint32_t soA0 = swz(lrow, lc), soA1 = swz(lrow + 64, lc);
    const uint32_t soB0 = 8192 + soA0, soB1 = 8192 + soA1;

    auto load = [&](int kt, int st) {
        const uint32_t sb = su + (uint32_t)st * STAGE_B;
        const int ko = kt * 32;
        cp16(sb + soA0, pa0 + ko);
        cp16(sb + soA1, pa1 + ko);
        cp16(sb + soB0, pb0 + ko);
        cp16(sb + soB1, pb1 + ko);
        CP_COMMIT();
    };

    int aoff[4], axr[4];
#pragma unroll
    for (int i = 0; i < 4; i++) {
        int r = wm * 64 + i * 16 + lane15;
        aoff[i] = r * 64; axr[i] = (r >> 1) & 3;
    }
    int boff[2], bxr[2];
#pragma unroll
    for (int j = 0; j < 2; j++) {
        int r = wn * 32 + j * 16 + lane15;
        boff[j] = 8192 + r * 64; bxr[j] = (r >> 1) & 3;
    }

    float c[4][4][4] = {};

    const int NT = N_DIM / 32;   // 44
    load(0, 0); load(1, 1);
    for (int kt = 0; kt < NT; ++kt) {
        if (kt + 2 < NT) { CP_WAIT1(); } else { CP_WAIT0(); }
        __syncthreads();
        if (kt + 2 < NT) load(kt + 2, (kt + 2) % 3);

        const uint32_t sb = su + (uint32_t)(kt % 3) * STAGE_B;
#pragma unroll
        for (int kh = 0; kh < 2; ++kh) {
            const int ch = 2 * kh + lhi;
            uint32_t b0[4], b1[4];
            ldsm4(b0, sb + boff[0] + ((ch ^ bxr[0]) << 4));
            ldsm4(b1, sb + boff[1] + ((ch ^ bxr[1]) << 4));
#pragma unroll
            for (int i = 0; i < 4; i++) {
                uint32_t a[4];
                ldsm4(a, sb + aoff[i] + ((ch ^ axr[i]) << 4));
                mma16816(c[i][0], a, b0[0], b0[2]);
                mma16816(c[i][1], a, b0[1], b0[3]);
                mma16816(c[i][2], a, b1[0], b1[2]);
                mma16816(c[i][3], a, b1[1], b1[3]);
            }
        }
    }

    // epilogue: plain float2 stores into stage buffer
#pragma unroll
    for (int i = 0; i < 4; i++) {
        int r0 = wm * 64 + i * 16 + gq, r1 = r0 + 8;
        bool v0 = (m0 + r0) < cnt, v1 = (m0 + r1) < cnt;
        float* o0 = g_stage + ((size_t)e * CAP + m0 + r0) * K_DIM + n0;
        float* o1 = g_stage + ((size_t)e * CAP + m0 + r1) * K_DIM + n0;
#pragma unroll
        for (int j = 0; j < 4; j++) {
            int col = wn * 32 + j * 8 + tg * 2;
            if (v0) *(float2*)(o0 + col) = make_float2(c[i][j][0], c[i][j][1]);
            if (v1) *(float2*)(o1 + col) = make_float2(c[i][j][2], c[i][j][3]);
        }
    }
}

// combine: out[t] = gate0 * stage[slot0] + gate1 * stage[slot1]
__global__ void __launch_bounds__(256) combine_kernel(const float* __restrict__ gate,
                                                      float* __restrict__ out) {
    int gid = blockIdx.x * 256 + threadIdx.x;    // over M*K/4
    int t = gid >> 9;                            // K/4 = 512
    int c = (gid & 511) * 4;
    int s0 = g_slot[2 * t], s1 = g_slot[2 * t + 1];
    float g0 = gate[2 * t], g1 = gate[2 * t + 1];
    float4 acc = make_float4(0.f, 0.f, 0.f, 0.f);
    if (s0 >= 0) {
        float4 a = *(const float4*)(g_stage + (size_t)s0 * K_DIM + c);
        acc.x = g0 * a.x; acc.y = g0 * a.y; acc.z = g0 * a.z; acc.w = g0 * a.w;
    }
    if (s1 >= 0) {
        float4 b = *(const float4*)(g_stage + (size_t)s1 * K_DIM + c);
        acc.x += g1 * b.x; acc.y += g1 * b.y; acc.z += g1 * b.z; acc.w += g1 * b.w;
    }
    *(float4*)(out + (size_t)t * K_DIM + c) = acc;
}

// ---------------------------------------------------------------------------
extern "C" void kernel_launch(void* const* d_in, const int* in_sizes, int n_in,
                              void* d_out, int out_size) {
    const float* H   = (const float*)d_in[0];
    const int*   IDX = (const int*)  d_in[1];
    const float* G   = (const float*)d_in[2];
    const float* GW  = (const float*)d_in[3];
    const float* UW  = (const float*)d_in[4];
    const float* DW  = (const float*)d_in[5];
    float* OUT = (float*)d_out;

    const int gsm = 3 * STAGE_B;
    cudaFuncSetAttribute(gemm1_tc, cudaFuncAttributeMaxDynamicSharedMemorySize, gsm);
    cudaFuncSetAttribute(gemm2_tc, cudaFuncAttributeMaxDynamicSharedMemorySize, gsm);

    dim3 cw(W_ELEMS / 4 / 256, 3);                 // 22528 x 3
    convw<<<cw, 256>>>(GW, UW, DW);
    zero_cnt<<<1, 32>>>();
    route_kernel<<<(N_ROWS + 255) / 256, 256>>>(IDX);
    gather_x<<<N_ROWS, 128>>>(H);

    dim3 g1(N_DIM / 64, CAP / 128, N_EXP);         // 22 x 8 x 8
    gemm1_tc<<<g1, 256, gsm>>>();
    dim3 g2(K_DIM / 128, CAP / 128, N_EXP);        // 16 x 8 x 8
    gemm2_tc<<<g2, 256, gsm>>>();

    combine_kernel<<<M_TOK * K_DIM / 4 / 256, 256>>>(G, OUT);
}

// round 6
// speedup vs baseline: 5.0375x; 1.0184x over previous
#include <cuda_runtime.h>
#include <cuda_fp16.h>
#include <cstdint>

// ---------------- problem constants ----------------
#define M_TOK 2048
#define K_DIM 2048
#define N_DIM 1408
#define N_EXP 8
#define TOP_K 2
#define CAP   1024
#define N_ROWS (M_TOK * TOP_K)
#define W_ELEMS (N_EXP * N_DIM * K_DIM)

// ---------------- scratch ----------------
__device__ int    g_cnt[N_EXP];
__device__ int    g_slot[N_ROWS];
__device__ __half g_x16 [(size_t)N_EXP * CAP * K_DIM];     // dispatched rows fp16
__device__ __half g_act [(size_t)N_EXP * CAP * N_DIM];     // SwiGLU acts fp16
__device__ __half g_stage[(size_t)N_EXP * CAP * K_DIM];    // down out fp16 (32MB)
__device__ __half g_gw16[W_ELEMS];
__device__ __half g_uw16[W_ELEMS];
__device__ __half g_dw16[W_ELEMS];

// ---------------- helpers (baseline sm_80 ISA) ----------------
__device__ __forceinline__ uint32_t smem_u32(const void* p) {
    uint32_t a;
    asm("{ .reg .u64 t; cvta.to.shared.u64 t, %1; cvt.u32.u64 %0, t; }" : "=r"(a) : "l"(p));
    return a;
}
__device__ __forceinline__ void cp16(uint32_t s, const void* g) {
    asm volatile("cp.async.cg.shared.global [%0], [%1], 16;" :: "r"(s), "l"(g));
}
#define CP_COMMIT() asm volatile("cp.async.commit_group;" ::: "memory")
#define CP_WAIT2()  asm volatile("cp.async.wait_group 2;" ::: "memory")
#define CP_WAIT1()  asm volatile("cp.async.wait_group 1;" ::: "memory")
#define CP_WAIT0()  asm volatile("cp.async.wait_group 0;" ::: "memory")
__device__ __forceinline__ void ldsm4(uint32_t* r, uint32_t addr) {
    asm volatile("ldmatrix.sync.aligned.m8n8.x4.shared.b16 {%0,%1,%2,%3}, [%4];"
                 : "=r"(r[0]), "=r"(r[1]), "=r"(r[2]), "=r"(r[3]) : "r"(addr));
}
__device__ __forceinline__ void mma16816(float* c, const uint32_t* a, uint32_t b0, uint32_t b1) {
    asm volatile("mma.sync.aligned.m16n8k16.row.col.f32.f16.f16.f32 "
        "{%0,%1,%2,%3},{%4,%5,%6,%7},{%8,%9},{%0,%1,%2,%3};"
        : "+f"(c[0]), "+f"(c[1]), "+f"(c[2]), "+f"(c[3])
        : "r"(a[0]), "r"(a[1]), "r"(a[2]), "r"(a[3]), "r"(b0), "r"(b1));
}
__device__ __forceinline__ uint2 pk4(float4 v) {
    __half2 h0 = __floats2half2_rn(v.x, v.y), h1 = __floats2half2_rn(v.z, v.w);
    return make_uint2(*reinterpret_cast<uint32_t*>(&h0), *reinterpret_cast<uint32_t*>(&h1));
}
__device__ __forceinline__ float swiglu(float g, float u) {
    g = fminf(g, 10.0f);
    u = fminf(fmaxf(u, -10.0f), 10.0f);
    return (g / (1.0f + __expf(-g))) * u;
}
__device__ __forceinline__ uint32_t swz(int row, int c) {
    return (uint32_t)(row * 64 + ((c ^ ((row >> 1) & 3)) << 4));
}

// ---------------- prep kernels ----------------
__global__ void zero_cnt() { if (threadIdx.x < N_EXP) g_cnt[threadIdx.x] = 0; }

__global__ void route_kernel(const int* __restrict__ idx) {
    int r = blockIdx.x * 256 + threadIdx.x;
    if (r >= N_ROWS) return;
    int e = idx[r];
    int p = atomicAdd(&g_cnt[e], 1);
    g_slot[r] = (p < CAP) ? (e * CAP + p) : -1;
}

__global__ void __launch_bounds__(128) gather_x(const float* __restrict__ H) {
    const int r = blockIdx.x;
    const int s = g_slot[r];
    if (s < 0) return;
    const float4* src = (const float4*)(H + (size_t)(r >> 1) * K_DIM);
    uint2* dst = (uint2*)(g_x16 + (size_t)s * K_DIM);
#pragma unroll
    for (int i = 0; i < 4; i++) {
        int q = threadIdx.x + i * 128;
        dst[q] = pk4(src[q]);
    }
}

__global__ void __launch_bounds__(256) convw(const float* __restrict__ GW,
                                             const float* __restrict__ UW,
                                             const float* __restrict__ DW) {
    const float* src = (blockIdx.y == 0) ? GW : (blockIdx.y == 1) ? UW : DW;
    __half* dst = (blockIdx.y == 0) ? g_gw16 : (blockIdx.y == 1) ? g_uw16 : g_dw16;
    size_t q = (size_t)blockIdx.x * 256 + threadIdx.x;
    float4 v = ((const float4*)src)[q];
    ((uint2*)dst)[q] = pk4(v);
}

// ---------------- GEMMs (4-stage cp.async pipeline) ----------------
#define STAGE_B 16384
#define NSTAGE  4
extern __shared__ char smc[];

// tail-exact wait: stage kt must be complete
__device__ __forceinline__ void pipe_wait(int kt, int NT) {
    int rem = NT - 1 - kt;
    if (rem >= 2)      CP_WAIT2();
    else if (rem == 1) CP_WAIT1();
    else               CP_WAIT0();
}

// GEMM1: G = X@GW^T, U = X@UW^T (CTA 128m x 64n each), SwiGLU -> g_act
// stage: A(128rows)@0  G(64)@8192  U(64)@12288  (rows of 32 fp16)
__global__ void __launch_bounds__(256, 2) gemm1_tc() {
    const int e = blockIdx.z;
    int cnt = g_cnt[e]; if (cnt > CAP) cnt = CAP;
    const int m0 = blockIdx.x * 128;          // m fastest: consecutive CTAs share B
    if (m0 >= cnt) return;
    const int n0 = blockIdx.y * 64;

    const int tid = threadIdx.x, lane = tid & 31, wid = tid >> 5;
    const int wm = wid >> 2, wn = wid & 3;
    const int gq = lane >> 2, tg = lane & 3;
    const int lane15 = lane & 15, lhi = lane >> 4;

    const uint32_t su = smem_u32(smc);

    const int lrow = tid >> 2, lc = tid & 3;
    const __half* pa0 = g_x16 + ((size_t)(e * CAP + m0) + lrow) * K_DIM + lc * 8;
    const __half* pa1 = pa0 + (size_t)64 * K_DIM;
    const __half* pg  = g_gw16 + ((size_t)e * N_DIM + n0 + lrow) * K_DIM + lc * 8;
    const __half* pu  = g_uw16 + ((size_t)e * N_DIM + n0 + lrow) * K_DIM + lc * 8;
    const uint32_t soA0 = swz(lrow, lc), soA1 = swz(lrow + 64, lc);
    const uint32_t soG = 8192 + swz(lrow, lc), soU = 12288 + swz(lrow, lc);

    auto load = [&](int kt) {
        const uint32_t sb = su + (uint32_t)(kt % NSTAGE) * STAGE_B;
        const int ko = kt * 32;
        cp16(sb + soA0, pa0 + ko);
        cp16(sb + soA1, pa1 + ko);
        cp16(sb + soG,  pg  + ko);
        cp16(sb + soU,  pu  + ko);
        CP_COMMIT();
    };

    int aoff[4], axr[4];
#pragma unroll
    for (int i = 0; i < 4; i++) {
        int r = wm * 64 + i * 16 + lane15;
        aoff[i] = r * 64; axr[i] = (r >> 1) & 3;
    }
    const int brw = wn * 16 + lane15;
    const int boff = brw * 64, bxr = (brw >> 1) & 3;

    float cG[4][2][4] = {}, cU[4][2][4] = {};

    const int NT = K_DIM / 32;   // 64
    load(0); load(1); load(2);
    for (int kt = 0; kt < NT; ++kt) {
        pipe_wait(kt, NT);
        __syncthreads();
        if (kt + 3 < NT) load(kt + 3);

        const uint32_t sb = su + (uint32_t)(kt % NSTAGE) * STAGE_B;
#pragma unroll
        for (int kh = 0; kh < 2; ++kh) {
            const int ch = 2 * kh + lhi;
            uint32_t bg[4], bu[4];
            ldsm4(bg, sb + 8192  + boff + ((ch ^ bxr) << 4));
            ldsm4(bu, sb + 12288 + boff + ((ch ^ bxr) << 4));
#pragma unroll
            for (int i = 0; i < 4; i++) {
                uint32_t a[4];
                ldsm4(a, sb + aoff[i] + ((ch ^ axr[i]) << 4));
                mma16816(cG[i][0], a, bg[0], bg[2]);
                mma16816(cG[i][1], a, bg[1], bg[3]);
                mma16816(cU[i][0], a, bu[0], bu[2]);
                mma16816(cU[i][1], a, bu[1], bu[3]);
            }
        }
    }

#pragma unroll
    for (int i = 0; i < 4; i++) {
        int r0 = wm * 64 + i * 16 + gq;
        int mg0 = m0 + r0, mg1 = mg0 + 8;
        __half* row0 = g_act + ((size_t)e * CAP + mg0) * N_DIM + n0;
        __half* row1 = g_act + ((size_t)e * CAP + mg1) * N_DIM + n0;
#pragma unroll
        for (int j = 0; j < 2; j++) {
            int col = wn * 16 + j * 8 + tg * 2;
            if (mg0 < cnt)
                *(__half2*)(row0 + col) = __floats2half2_rn(
                    swiglu(cG[i][j][0], cU[i][j][0]), swiglu(cG[i][j][1], cU[i][j][1]));
            if (mg1 < cnt)
                *(__half2*)(row1 + col) = __floats2half2_rn(
                    swiglu(cG[i][j][2], cU[i][j][2]), swiglu(cG[i][j][3], cU[i][j][3]));
        }
    }
}

// GEMM2: D = act@DW^T (CTA 128m x 128n) -> g_stage (fp16, plain stores)
// stage: A(128rows)@0  B(128rows)@8192
__global__ void __launch_bounds__(256, 2) gemm2_tc() {
    const int e = blockIdx.z;
    int cnt = g_cnt[e]; if (cnt > CAP) cnt = CAP;
    const int m0 = blockIdx.x * 128;          // m fastest
    if (m0 >= cnt) return;
    const int n0 = blockIdx.y * 128;

    const int tid = threadIdx.x, lane = tid & 31, wid = tid >> 5;
    const int wm = wid >> 2, wn = wid & 3;
    const int gq = lane >> 2, tg = lane & 3;
    const int lane15 = lane & 15, lhi = lane >> 4;

    const uint32_t su = smem_u32(smc);

    const int lrow = tid >> 2, lc = tid & 3;
    const __half* pa0 = g_act + ((size_t)(e * CAP + m0) + lrow) * N_DIM + lc * 8;
    const __half* pa1 = pa0 + (size_t)64 * N_DIM;
    const __half* pb0 = g_dw16 + ((size_t)e * K_DIM + n0 + lrow) * N_DIM + lc * 8;
    const __half* pb1 = pb0 + (size_t)64 * N_DIM;
    const uint32_t soA0 = swz(lrow, lc), soA1 = swz(lrow + 64, lc);
    const uint32_t soB0 = 8192 + soA0, soB1 = 8192 + soA1;

    auto load = [&](int kt) {
        const uint32_t sb = su + (uint32_t)(kt % NSTAGE) * STAGE_B;
        const int ko = kt * 32;
        cp16(sb + soA0, pa0 + ko);
        cp16(sb + soA1, pa1 + ko);
        cp16(sb + soB0, pb0 + ko);
        cp16(sb + soB1, pb1 + ko);
        CP_COMMIT();
    };

    int aoff[4], axr[4];
#pragma unroll
    for (int i = 0; i < 4; i++) {
        int r = wm * 64 + i * 16 + lane15;
        aoff[i] = r * 64; axr[i] = (r >> 1) & 3;
    }
    int boff[2], bxr[2];
#pragma unroll
    for (int j = 0; j < 2; j++) {
        int r = wn * 32 + j * 16 + lane15;
        boff[j] = 8192 + r * 64; bxr[j] = (r >> 1) & 3;
    }

    float c[4][4][4] = {};

    const int NT = N_DIM / 32;   // 44
    load(0); load(1); load(2);
    for (int kt = 0; kt < NT; ++kt) {
        pipe_wait(kt, NT);
        __syncthreads();
        if (kt + 3 < NT) load(kt + 3);

        const uint32_t sb = su + (uint32_t)(kt % NSTAGE) * STAGE_B;
#pragma unroll
        for (int kh = 0; kh < 2; ++kh) {
            const int ch = 2 * kh + lhi;
            uint32_t b0[4], b1[4];
            ldsm4(b0, sb + boff[0] + ((ch ^ bxr[0]) << 4));
            ldsm4(b1, sb + boff[1] + ((ch ^ bxr[1]) << 4));
#pragma unroll
            for (int i = 0; i < 4; i++) {
                uint32_t a[4];
                ldsm4(a, sb + aoff[i] + ((ch ^ axr[i]) << 4));
                mma16816(c[i][0], a, b0[0], b0[2]);
                mma16816(c[i][1], a, b0[1], b0[3]);
                mma16816(c[i][2], a, b1[0], b1[2]);
                mma16816(c[i][3], a, b1[1], b1[3]);
            }
        }
    }

    // epilogue: fp16 stores into stage buffer
#pragma unroll
    for (int i = 0; i < 4; i++) {
        int r0 = wm * 64 + i * 16 + gq, r1 = r0 + 8;
        bool v0 = (m0 + r0) < cnt, v1 = (m0 + r1) < cnt;
        __half* o0 = g_stage + ((size_t)e * CAP + m0 + r0) * K_DIM + n0;
        __half* o1 = g_stage + ((size_t)e * CAP + m0 + r1) * K_DIM + n0;
#pragma unroll
        for (int j = 0; j < 4; j++) {
            int col = wn * 32 + j * 8 + tg * 2;
            if (v0) *(__half2*)(o0 + col) = __floats2half2_rn(c[i][j][0], c[i][j][1]);
            if (v1) *(__half2*)(o1 + col) = __floats2half2_rn(c[i][j][2], c[i][j][3]);
        }
    }
}

// combine: out[t] = gate0 * stage[slot0] + gate1 * stage[slot1]   (fp16 stage)
__global__ void __launch_bounds__(256) combine_kernel(const float* __restrict__ gate,
                                                      float* __restrict__ out) {
    int gid = blockIdx.x * 256 + threadIdx.x;    // over M*K/8
    int t = gid >> 8;                            // K/8 = 256
    int c = (gid & 255) * 8;
    int s0 = g_slot[2 * t], s1 = g_slot[2 * t + 1];
    float g0 = gate[2 * t], g1 = gate[2 * t + 1];
    float acc[8] = {0, 0, 0, 0, 0, 0, 0, 0};
    if (s0 >= 0) {
        uint4 v = *(const uint4*)(g_stage + (size_t)s0 * K_DIM + c);
        const __half2* h = (const __half2*)&v;
#pragma unroll
        for (int q = 0; q < 4; q++) {
            float2 f = __half22float2(h[q]);
            acc[2 * q]     = g0 * f.x;
            acc[2 * q + 1] = g0 * f.y;
        }
    }
    if (s1 >= 0) {
        uint4 v = *(const uint4*)(g_stage + (size_t)s1 * K_DIM + c);
        const __half2* h = (const __half2*)&v;
#pragma unroll
        for (int q = 0; q < 4; q++) {
            float2 f = __half22float2(h[q]);
            acc[2 * q]     += g1 * f.x;
            acc[2 * q + 1] += g1 * f.y;
        }
    }
    float4* po = (float4*)(out + (size_t)t * K_DIM + c);
    po[0] = make_float4(acc[0], acc[1], acc[2], acc[3]);
    po[1] = make_float4(acc[4], acc[5], acc[6], acc[7]);
}

// ---------------------------------------------------------------------------
extern "C" void kernel_launch(void* const* d_in, const int* in_sizes, int n_in,
                              void* d_out, int out_size) {
    const int*   IDX = (const int*)  d_in[1];
    const float* H   = (const float*)d_in[0];
    const float* G   = (const float*)d_in[2];
    const float* GW  = (const float*)d_in[3];
    const float* UW  = (const float*)d_in[4];
    const float* DW  = (const float*)d_in[5];
    float* OUT = (float*)d_out;

    const int gsm = NSTAGE * STAGE_B;   // 64KB
    cudaFuncSetAttribute(gemm1_tc, cudaFuncAttributeMaxDynamicSharedMemorySize, gsm);
    cudaFuncSetAttribute(gemm2_tc, cudaFuncAttributeMaxDynamicSharedMemorySize, gsm);

    dim3 cw(W_ELEMS / 4 / 256, 3);
    convw<<<cw, 256>>>(GW, UW, DW);
    zero_cnt<<<1, 32>>>();
    route_kernel<<<(N_ROWS + 255) / 256, 256>>>(IDX);
    gather_x<<<N_ROWS, 128>>>(H);

    dim3 g1(CAP / 128, N_DIM / 64, N_EXP);         // m fastest: 8 x 22 x 8
    gemm1_tc<<<g1, 256, gsm>>>();
    dim3 g2(CAP / 128, K_DIM / 128, N_EXP);        // 8 x 16 x 8
    gemm2_tc<<<g2, 256, gsm>>>();

    combine_kernel<<<M_TOK * K_DIM / 8 / 256, 256>>>(G, OUT);
}